// round 5
// baseline (speedup 1.0000x reference)
#include <cuda_runtime.h>

// Problem constants (fixed by the dataset)
#define NN      262144            // nodes per tree (2^18)
#define NT      12                // B*C trees
#define HWPX    1048576           // H*W (2^20)
#define T0      2048              // exactly-solved prefix per tree (2^11)
#define TOTAL   (NT * NN)

// PDL intrinsics (sm_90+). Trigger at entry so dependents can launch early;
// wait only where a true data dependency on the predecessor exists.
#define PDL_TRIGGER() asm volatile("griddepcontrol.launch_dependents;" ::: "memory")
#define PDL_WAIT()    asm volatile("griddepcontrol.wait;" ::: "memory")

// Scratch (allocation-free rule: __device__ globals)
__device__ float4 g_node[TOTAL];   // {c0,c1,c2,parent-as-float-bits}
__device__ float4 g_F[TOTAL];      // final {f0,f1,f2,_}

__device__ __forceinline__ float sigmoidf_(float x) {
    return 1.0f / (1.0f + expf(-x));
}

// ---------------------------------------------------------------------------
// Kernel A (per tree): scores -> contrib, packed with parent pointer.
// 4 nodes/thread. No data dependency on predecessor -> no PDL_WAIT.
// grid = 256 x 256 threads.
// ---------------------------------------------------------------------------
__global__ void k_contrib(int tree,
                          const float4* __restrict__ attrs4,
                          const float4* __restrict__ residue4,
                          const int4*  __restrict__ parent4,
                          const float* __restrict__ W0,
                          const float* __restrict__ W1,
                          const float* __restrict__ W2,
                          const float* __restrict__ b0,
                          const float* __restrict__ b1,
                          const float* __restrict__ b2) {
    PDL_TRIGGER();
    size_t q = (size_t)tree * (NN / 4) + blockIdx.x * blockDim.x + threadIdx.x;

    float4 A0 = __ldcs(&attrs4[3 * q + 0]);   // a0[0] a1[0] a2[0] a0[1]
    float4 A1 = __ldcs(&attrs4[3 * q + 1]);   // a1[1] a2[1] a0[2] a1[2]
    float4 A2 = __ldcs(&attrs4[3 * q + 2]);   // a2[2] a0[3] a1[3] a2[3]
    float4 R  = __ldcs(&residue4[q]);
    int4   P  = __ldcs(&parent4[q]);

    const float w0  = __ldg(W0);
    const float w10 = __ldg(&W1[0]);
    const float w11 = __ldg(&W1[1]);
    const float w2  = __ldg(W2);
    const float B0 = __ldg(b0), B1 = __ldg(b1), B2 = __ldg(b2);

    float a0[4] = {A0.x, A0.w, A1.z, A2.y};
    float a1[4] = {A0.y, A1.x, A1.w, A2.z};
    float a2[4] = {A0.z, A1.y, A2.x, A2.w};
    float r[4]  = {R.x, R.y, R.z, R.w};
    int   p[4]  = {P.x, P.y, P.z, P.w};

    float4* outp = g_node + 4 * q;
#pragma unroll
    for (int k = 0; k < 4; k++) {
        float c0 = sigmoidf_(fmaf(a0[k], w0, B0)) * r[k];
        float c1 = sigmoidf_(fmaf(a2[k], w11, fmaf(a1[k], w10, B1))) * r[k];
        float c2 = sigmoidf_(fmaf(a1[k], w2, B2)) * r[k];
        outp[k] = make_float4(c0, c1, c2, __int_as_float(p[k]));
    }
}

// ---------------------------------------------------------------------------
// Kernel B (per tree): exact prefix for nodes [0,T0), in-smem Wyllie jumping.
// grid = 1 x 1024 threads. Waits on contrib(tree).
// ---------------------------------------------------------------------------
__global__ void __launch_bounds__(1024, 1) k_prefix(int tree) {
    PDL_TRIGGER();
    PDL_WAIT();

    __shared__ float4 sm[T0];
    const float4* nb = g_node + (size_t)tree * NN;

    for (int i = threadIdx.x; i < T0; i += blockDim.x)
        sm[i] = nb[i];
    __syncthreads();

    const int e0 = threadIdx.x;
    const int e1 = threadIdx.x + 1024;

    for (int r = 0; r < 11; r++) {
        float4 v0 = sm[e0];
        float4 v1 = sm[e1];
        int p0 = __float_as_int(v0.w);
        int p1 = __float_as_int(v1.w);
        if (p0 < T0) {
            float4 o = sm[p0];
            v0.x += o.x; v0.y += o.y; v0.z += o.z; v0.w = o.w;
        }
        if (p1 < T0) {
            float4 o = sm[p1];
            v1.x += o.x; v1.y += o.y; v1.z += o.z; v1.w = o.w;
        }
        __syncthreads();
        sm[e0] = v0;
        sm[e1] = v1;
        __syncthreads();
    }

    float4* Fb = g_F + (size_t)tree * NN;
    for (int i = threadIdx.x; i < T0; i += blockDim.x) {
        float4 v = sm[i];
        Fb[i] = make_float4(v.x, v.y, v.z, 0.0f);
    }
}

// ---------------------------------------------------------------------------
// Kernel C (per tree, per stage): finalize F for [start, start+grid*256).
// Everything below `start` is final in g_F. Waits on predecessor stage.
// ---------------------------------------------------------------------------
__global__ void k_cascade(int tree, int start) {
    PDL_TRIGGER();
    PDL_WAIT();

    const int n = start + blockIdx.x * blockDim.x + threadIdx.x;
    const float4* nb = g_node + (size_t)tree * NN;
    float4*       Fb = g_F    + (size_t)tree * NN;

    float4 v = __ldg(&nb[n]);
    float ax = v.x, ay = v.y, az = v.z;
    int p = __float_as_int(v.w);

    while (p >= start) {
        float4 u = __ldg(&nb[p]);
        ax += u.x; ay += u.y; az += u.z;
        p = __float_as_int(u.w);
    }
    float4 f = __ldg(&Fb[p]);
    Fb[n] = make_float4(ax + f.x, ay + f.y, az + f.z, 0.0f);
}

// ---------------------------------------------------------------------------
// Kernel D (per tree): pixel gather, 4 pixels/thread, one 16B gather serves
// all 3 output channels; coalesced float4 stores per channel plane.
// grid = 1024 x 256 threads. Waits on last cascade stage of this tree.
// ---------------------------------------------------------------------------
__global__ void k_gather(int tree,
                         const int4* __restrict__ pix4,
                         float* __restrict__ out) {
    PDL_TRIGGER();
    PDL_WAIT();

    const int lt = blockIdx.x * blockDim.x + threadIdx.x;  // quad idx in tree
    int4 nd = __ldcs(&pix4[(size_t)tree * (HWPX / 4) + lt]);

    const float4* Fb = g_F + (size_t)tree * NN;
    float4 F0 = __ldg(&Fb[nd.x]);
    float4 F1 = __ldg(&Fb[nd.y]);
    float4 F2 = __ldg(&Fb[nd.z]);
    float4 F3 = __ldg(&Fb[nd.w]);

    float* o = out + (size_t)tree * 3 * HWPX + 4 * (size_t)lt;
    __stcs((float4*)(o),            make_float4(F0.x, F1.x, F2.x, F3.x));
    __stcs((float4*)(o + HWPX),     make_float4(F0.y, F1.y, F2.y, F3.y));
    __stcs((float4*)(o + 2 * HWPX), make_float4(F0.z, F1.z, F2.z, F3.z));
}

// ---------------------------------------------------------------------------
// Entry point: 12 independent per-tree chains, PDL-linked so gather(t)
// overlaps the compute chain of tree t+1.
// Inputs: attrs, residue, W0, W1, W2, b0, b1, b2, parent, pixel_node
// ---------------------------------------------------------------------------
extern "C" void kernel_launch(void* const* d_in, const int* in_sizes, int n_in,
                              void* d_out, int out_size) {
    const float4* attrs4   = (const float4*)d_in[0];
    const float4* residue4 = (const float4*)d_in[1];
    const float* W0        = (const float*)d_in[2];
    const float* W1        = (const float*)d_in[3];
    const float* W2        = (const float*)d_in[4];
    const float* b0        = (const float*)d_in[5];
    const float* b1        = (const float*)d_in[6];
    const float* b2        = (const float*)d_in[7];
    const int4*  parent4   = (const int4*)d_in[8];
    const int4*  pix4      = (const int4*)d_in[9];
    float*       out       = (float*)d_out;

    cudaLaunchAttribute pdl[1];
    pdl[0].id = cudaLaunchAttributeProgrammaticStreamSerialization;
    pdl[0].val.programmaticStreamSerializationAllowed = 1;

    cudaLaunchConfig_t cfg = {};
    cfg.blockDim = dim3(256, 1, 1);
    cfg.dynamicSmemBytes = 0;
    cfg.stream = 0;
    cfg.attrs = pdl;
    cfg.numAttrs = 1;

    // Cascade stage starts; stage s covers [st[s], st[s+1]).
    const int st[5] = {2048, 8192, 32768, 131072, 262144};

    for (int t = 0; t < NT; t++) {
        cfg.gridDim = dim3(256, 1, 1);                    // NN/4/256
        cudaLaunchKernelEx(&cfg, k_contrib, t, attrs4, residue4, parent4,
                           W0, W1, W2, b0, b1, b2);

        {
            cudaLaunchConfig_t pcfg = cfg;
            pcfg.gridDim = dim3(1, 1, 1);
            pcfg.blockDim = dim3(1024, 1, 1);
            cudaLaunchKernelEx(&pcfg, k_prefix, t);
        }

        for (int s = 0; s < 4; s++) {
            cfg.gridDim = dim3((st[s + 1] - st[s]) / 256, 1, 1);
            cudaLaunchKernelEx(&cfg, k_cascade, t, st[s]);
        }

        cfg.gridDim = dim3(1024, 1, 1);                   // HWPX/4/256
        cudaLaunchKernelEx(&cfg, k_gather, t, pix4, out);
    }
}

// round 6
// speedup vs baseline: 1.9319x; 1.9319x over previous
#include <cuda_runtime.h>

// Problem constants (fixed by the dataset)
#define NN      262144            // nodes per tree (2^18)
#define NT      12                // B*C trees
#define HWPX    1048576           // H*W (2^20)
#define T0      2048              // exactly-solved prefix per tree (2^11)
#define TOTAL   (NT * NN)
#define TPG     4                 // trees per pipeline group
#define NGRP    (NT / TPG)        // 3 groups

// Scratch (allocation-free rule: __device__ globals)
__device__ float4 g_node[TOTAL];   // {c0,c1,c2,parent-as-float-bits}
__device__ float4 g_F[TOTAL];      // final {f0,f1,f2,_}

__device__ __forceinline__ float sigmoidf_(float x) {
    return 1.0f / (1.0f + expf(-x));
}

// ---------------------------------------------------------------------------
// Kernel A (per group): scores -> contrib, packed with parent pointer.
// 4 nodes/thread. grid = TPG*NN/4/256 = 1024 blocks.
// ---------------------------------------------------------------------------
__global__ void k_contrib(int base,                       // first tree of group
                          const float4* __restrict__ attrs4,
                          const float4* __restrict__ residue4,
                          const int4*  __restrict__ parent4,
                          const float* __restrict__ W0,
                          const float* __restrict__ W1,
                          const float* __restrict__ W2,
                          const float* __restrict__ b0,
                          const float* __restrict__ b1,
                          const float* __restrict__ b2) {
    size_t q = (size_t)base * (NN / 4)
             + (size_t)blockIdx.x * blockDim.x + threadIdx.x;

    float4 A0 = __ldcs(&attrs4[3 * q + 0]);   // a0[0] a1[0] a2[0] a0[1]
    float4 A1 = __ldcs(&attrs4[3 * q + 1]);   // a1[1] a2[1] a0[2] a1[2]
    float4 A2 = __ldcs(&attrs4[3 * q + 2]);   // a2[2] a0[3] a1[3] a2[3]
    float4 R  = __ldcs(&residue4[q]);
    int4   P  = __ldcs(&parent4[q]);

    const float w0  = __ldg(W0);
    const float w10 = __ldg(&W1[0]);
    const float w11 = __ldg(&W1[1]);
    const float w2  = __ldg(W2);
    const float B0 = __ldg(b0), B1 = __ldg(b1), B2 = __ldg(b2);

    float a0[4] = {A0.x, A0.w, A1.z, A2.y};
    float a1[4] = {A0.y, A1.x, A1.w, A2.z};
    float a2[4] = {A0.z, A1.y, A2.x, A2.w};
    float r[4]  = {R.x, R.y, R.z, R.w};
    int   p[4]  = {P.x, P.y, P.z, P.w};

    float4* outp = g_node + 4 * q;
#pragma unroll
    for (int k = 0; k < 4; k++) {
        float c0 = sigmoidf_(fmaf(a0[k], w0, B0)) * r[k];
        float c1 = sigmoidf_(fmaf(a2[k], w11, fmaf(a1[k], w10, B1))) * r[k];
        float c2 = sigmoidf_(fmaf(a1[k], w2, B2)) * r[k];
        outp[k] = make_float4(c0, c1, c2, __int_as_float(p[k]));
    }
}

// ---------------------------------------------------------------------------
// Kernel B (per group): exact prefix for nodes [0,T0) per tree, in-smem
// Wyllie jumping. grid = TPG blocks x 1024 threads (block = tree).
// ---------------------------------------------------------------------------
__global__ void __launch_bounds__(1024, 1) k_prefix(int base) {
    __shared__ float4 sm[T0];
    const int tree = base + blockIdx.x;
    const float4* nb = g_node + (size_t)tree * NN;

    for (int i = threadIdx.x; i < T0; i += blockDim.x)
        sm[i] = nb[i];
    __syncthreads();

    const int e0 = threadIdx.x;
    const int e1 = threadIdx.x + 1024;

    for (int r = 0; r < 11; r++) {
        float4 v0 = sm[e0];
        float4 v1 = sm[e1];
        int p0 = __float_as_int(v0.w);
        int p1 = __float_as_int(v1.w);
        if (p0 < T0) {
            float4 o = sm[p0];
            v0.x += o.x; v0.y += o.y; v0.z += o.z; v0.w = o.w;
        }
        if (p1 < T0) {
            float4 o = sm[p1];
            v1.x += o.x; v1.y += o.y; v1.z += o.z; v1.w = o.w;
        }
        __syncthreads();
        sm[e0] = v0;
        sm[e1] = v1;
        __syncthreads();
    }

    float4* Fb = g_F + (size_t)tree * NN;
    for (int i = threadIdx.x; i < T0; i += blockDim.x) {
        float4 v = sm[i];
        Fb[i] = make_float4(v.x, v.y, v.z, 0.0f);
    }
}

// ---------------------------------------------------------------------------
// Kernel C (per group, per stage): finalize F for [start, start+gridDim.x*256)
// of trees [base, base+TPG). Everything below `start` is final in g_F.
// grid = (range/256, TPG).
// ---------------------------------------------------------------------------
__global__ void k_cascade(int base, int start) {
    const int tree = base + blockIdx.y;
    const int n = start + blockIdx.x * blockDim.x + threadIdx.x;

    const float4* nb = g_node + (size_t)tree * NN;
    float4*       Fb = g_F    + (size_t)tree * NN;

    float4 v = __ldg(&nb[n]);
    float ax = v.x, ay = v.y, az = v.z;
    int p = __float_as_int(v.w);

    while (p >= start) {
        float4 u = __ldg(&nb[p]);
        ax += u.x; ay += u.y; az += u.z;
        p = __float_as_int(u.w);
    }
    float4 f = __ldg(&Fb[p]);
    Fb[n] = make_float4(ax + f.x, ay + f.y, az + f.z, 0.0f);
}

// ---------------------------------------------------------------------------
// Kernel D (per group): pixel gather, 4 pixels/thread; one 16B gather serves
// all 3 output channels; coalesced float4 stores per channel plane.
// grid = (HWPX/4/256, TPG). Runs on the side stream, overlapping the next
// group's compute chain.
// ---------------------------------------------------------------------------
__global__ void k_gather(int base,
                         const int4* __restrict__ pix4,
                         float* __restrict__ out) {
    const int tree = base + blockIdx.y;
    const int lt = blockIdx.x * blockDim.x + threadIdx.x;   // quad idx in tree

    int4 nd = __ldcs(&pix4[(size_t)tree * (HWPX / 4) + lt]);

    const float4* Fb = g_F + (size_t)tree * NN;
    float4 F0 = __ldg(&Fb[nd.x]);
    float4 F1 = __ldg(&Fb[nd.y]);
    float4 F2 = __ldg(&Fb[nd.z]);
    float4 F3 = __ldg(&Fb[nd.w]);

    float* o = out + (size_t)tree * 3 * HWPX + 4 * (size_t)lt;
    __stcs((float4*)(o),            make_float4(F0.x, F1.x, F2.x, F3.x));
    __stcs((float4*)(o + HWPX),     make_float4(F0.y, F1.y, F2.y, F3.y));
    __stcs((float4*)(o + 2 * HWPX), make_float4(F0.z, F1.z, F2.z, F3.z));
}

// ---------------------------------------------------------------------------
// Entry point: 3 groups of 4 trees. Compute chain per group on the capture
// stream; gathers on a capture-forked side stream so gather(G) overlaps
// compute(G+1). Fork/join via disable-timing events (graph-capture idiom).
// Inputs: attrs, residue, W0, W1, W2, b0, b1, b2, parent, pixel_node
// ---------------------------------------------------------------------------
extern "C" void kernel_launch(void* const* d_in, const int* in_sizes, int n_in,
                              void* d_out, int out_size) {
    const float4* attrs4   = (const float4*)d_in[0];
    const float4* residue4 = (const float4*)d_in[1];
    const float* W0        = (const float*)d_in[2];
    const float* W1        = (const float*)d_in[3];
    const float* W2        = (const float*)d_in[4];
    const float* b0        = (const float*)d_in[5];
    const float* b1        = (const float*)d_in[6];
    const float* b2        = (const float*)d_in[7];
    const int4*  parent4   = (const int4*)d_in[8];
    const int4*  pix4      = (const int4*)d_in[9];
    float*       out       = (float*)d_out;

    // Side stream + events. kernel_launch is only invoked a handful of times
    // (correctness + capture), so creating (and not destroying, since capture
    // is still in flight when we return) these tiny host-side resources per
    // call is safe and allocation-rule-clean (no device memory).
    cudaStream_t sb;
    cudaStreamCreateWithFlags(&sb, cudaStreamNonBlocking);

    cudaEvent_t evFork, evJoin, evC[NGRP];
    cudaEventCreateWithFlags(&evFork, cudaEventDisableTiming);
    cudaEventCreateWithFlags(&evJoin, cudaEventDisableTiming);
    for (int g = 0; g < NGRP; g++)
        cudaEventCreateWithFlags(&evC[g], cudaEventDisableTiming);

    // Fork side stream from the capture stream.
    cudaEventRecord(evFork, 0);
    cudaStreamWaitEvent(sb, evFork, 0);

    // Cascade stage starts; stage s covers [st[s], st[s+1]).
    const int st[4] = {2048, 16384, 131072, 262144};

    for (int g = 0; g < NGRP; g++) {
        const int base = g * TPG;

        k_contrib<<<TPG * (NN / 4) / 256, 256>>>(base, attrs4, residue4, parent4,
                                                 W0, W1, W2, b0, b1, b2);
        k_prefix<<<TPG, 1024>>>(base);
        for (int s = 0; s < 3; s++) {
            dim3 grid((st[s + 1] - st[s]) / 256, TPG);
            k_cascade<<<grid, 256>>>(base, st[s]);
        }

        cudaEventRecord(evC[g], 0);
        cudaStreamWaitEvent(sb, evC[g], 0);
        {
            dim3 grid(HWPX / 4 / 256, TPG);
            k_gather<<<grid, 256, 0, sb>>>(base, pix4, out);
        }
    }

    // Join side stream back into the capture stream.
    cudaEventRecord(evJoin, sb);
    cudaStreamWaitEvent(0, evJoin, 0);
}

// round 7
// speedup vs baseline: 2.3510x; 1.2169x over previous
#include <cuda_runtime.h>

// Problem constants (fixed by the dataset)
#define NN      262144            // nodes per tree (2^18)
#define NT      12                // B*C trees
#define HWPX    1048576           // H*W (2^20)
#define T0      2048              // exactly-solved prefix per tree (2^11)
#define TOTAL   (NT * NN)
#define TPG     4                 // trees per gather group
#define NGRP    (NT / TPG)        // 3 groups

// Scratch (allocation-free rule: __device__ globals)
__device__ float4 g_node[TOTAL];   // {c0,c1,c2,parent-as-float-bits}
__device__ float4 g_F[TOTAL];      // final {f0,f1,f2,_}

__device__ __forceinline__ float sigmoidf_(float x) {
    return 1.0f / (1.0f + expf(-x));
}

// ---------------------------------------------------------------------------
// Kernel A (full width): scores -> contrib, packed with parent pointer.
// 4 nodes/thread. grid = TOTAL/4/256 = 3072 blocks.
// ---------------------------------------------------------------------------
__global__ void k_contrib(const float4* __restrict__ attrs4,
                          const float4* __restrict__ residue4,
                          const int4*  __restrict__ parent4,
                          const float* __restrict__ W0,
                          const float* __restrict__ W1,
                          const float* __restrict__ W2,
                          const float* __restrict__ b0,
                          const float* __restrict__ b1,
                          const float* __restrict__ b2) {
    size_t q = (size_t)blockIdx.x * blockDim.x + threadIdx.x;

    float4 A0 = __ldcs(&attrs4[3 * q + 0]);   // a0[0] a1[0] a2[0] a0[1]
    float4 A1 = __ldcs(&attrs4[3 * q + 1]);   // a1[1] a2[1] a0[2] a1[2]
    float4 A2 = __ldcs(&attrs4[3 * q + 2]);   // a2[2] a0[3] a1[3] a2[3]
    float4 R  = __ldcs(&residue4[q]);
    int4   P  = __ldcs(&parent4[q]);

    const float w0  = __ldg(W0);
    const float w10 = __ldg(&W1[0]);
    const float w11 = __ldg(&W1[1]);
    const float w2  = __ldg(W2);
    const float B0 = __ldg(b0), B1 = __ldg(b1), B2 = __ldg(b2);

    float a0[4] = {A0.x, A0.w, A1.z, A2.y};
    float a1[4] = {A0.y, A1.x, A1.w, A2.z};
    float a2[4] = {A0.z, A1.y, A2.x, A2.w};
    float r[4]  = {R.x, R.y, R.z, R.w};
    int   p[4]  = {P.x, P.y, P.z, P.w};

    float4* outp = g_node + 4 * q;
#pragma unroll
    for (int k = 0; k < 4; k++) {
        float c0 = sigmoidf_(fmaf(a0[k], w0, B0)) * r[k];
        float c1 = sigmoidf_(fmaf(a2[k], w11, fmaf(a1[k], w10, B1))) * r[k];
        float c2 = sigmoidf_(fmaf(a1[k], w2, B2)) * r[k];
        outp[k] = make_float4(c0, c1, c2, __int_as_float(p[k]));
    }
}

// ---------------------------------------------------------------------------
// Kernel B (full width): exact prefix for nodes [0,T0) per tree, in-smem
// Wyllie jumping. grid = NT blocks x 1024 threads (block = tree).
// ---------------------------------------------------------------------------
__global__ void __launch_bounds__(1024, 1) k_prefix() {
    __shared__ float4 sm[T0];
    const int tree = blockIdx.x;
    const float4* nb = g_node + (size_t)tree * NN;

    for (int i = threadIdx.x; i < T0; i += blockDim.x)
        sm[i] = nb[i];
    __syncthreads();

    const int e0 = threadIdx.x;
    const int e1 = threadIdx.x + 1024;

    for (int r = 0; r < 11; r++) {
        float4 v0 = sm[e0];
        float4 v1 = sm[e1];
        int p0 = __float_as_int(v0.w);
        int p1 = __float_as_int(v1.w);
        if (p0 < T0) {
            float4 o = sm[p0];
            v0.x += o.x; v0.y += o.y; v0.z += o.z; v0.w = o.w;
        }
        if (p1 < T0) {
            float4 o = sm[p1];
            v1.x += o.x; v1.y += o.y; v1.z += o.z; v1.w = o.w;
        }
        __syncthreads();
        sm[e0] = v0;
        sm[e1] = v1;
        __syncthreads();
    }

    float4* Fb = g_F + (size_t)tree * NN;
    for (int i = threadIdx.x; i < T0; i += blockDim.x) {
        float4 v = sm[i];
        Fb[i] = make_float4(v.x, v.y, v.z, 0.0f);
    }
}

// ---------------------------------------------------------------------------
// Kernel C: finalize F for [start, start+gridDim.x*256) of trees
// [base, base+gridDim.y). Everything below `start` is final in g_F.
// ---------------------------------------------------------------------------
__global__ void k_cascade(int base, int start) {
    const int tree = base + blockIdx.y;
    const int n = start + blockIdx.x * blockDim.x + threadIdx.x;

    const float4* nb = g_node + (size_t)tree * NN;
    float4*       Fb = g_F    + (size_t)tree * NN;

    float4 v = __ldg(&nb[n]);
    float ax = v.x, ay = v.y, az = v.z;
    int p = __float_as_int(v.w);

    while (p >= start) {
        float4 u = __ldg(&nb[p]);
        ax += u.x; ay += u.y; az += u.z;
        p = __float_as_int(u.w);
    }
    float4 f = __ldg(&Fb[p]);
    Fb[n] = make_float4(ax + f.x, ay + f.y, az + f.z, 0.0f);
}

// ---------------------------------------------------------------------------
// Kernel D (per group): pixel gather, 4 pixels/thread; one 16B gather serves
// all 3 output channels; coalesced float4 stores per channel plane.
// grid = (HWPX/4/256, TPG). Runs on the side stream.
// ---------------------------------------------------------------------------
__global__ void k_gather(int base,
                         const int4* __restrict__ pix4,
                         float* __restrict__ out) {
    const int tree = base + blockIdx.y;
    const int lt = blockIdx.x * blockDim.x + threadIdx.x;   // quad idx in tree

    int4 nd = __ldcs(&pix4[(size_t)tree * (HWPX / 4) + lt]);

    const float4* Fb = g_F + (size_t)tree * NN;
    float4 F0 = __ldg(&Fb[nd.x]);
    float4 F1 = __ldg(&Fb[nd.y]);
    float4 F2 = __ldg(&Fb[nd.z]);
    float4 F3 = __ldg(&Fb[nd.w]);

    float* o = out + (size_t)tree * 3 * HWPX + 4 * (size_t)lt;
    __stcs((float4*)(o),            make_float4(F0.x, F1.x, F2.x, F3.x));
    __stcs((float4*)(o + HWPX),     make_float4(F0.y, F1.y, F2.y, F3.y));
    __stcs((float4*)(o + 2 * HWPX), make_float4(F0.z, F1.z, F2.z, F3.z));
}

// ---------------------------------------------------------------------------
// Entry point.
// Full-width compute (contrib, prefix, cascade s0/s1); only the LAST cascade
// stage is split into 3 groups of 4 trees, each releasing its gather group
// onto a capture-forked side stream. Gathers (the bottleneck) start after a
// ~30us head and the remaining s2 stages hide under them.
// Inputs: attrs, residue, W0, W1, W2, b0, b1, b2, parent, pixel_node
// ---------------------------------------------------------------------------
extern "C" void kernel_launch(void* const* d_in, const int* in_sizes, int n_in,
                              void* d_out, int out_size) {
    const float4* attrs4   = (const float4*)d_in[0];
    const float4* residue4 = (const float4*)d_in[1];
    const float* W0        = (const float*)d_in[2];
    const float* W1        = (const float*)d_in[3];
    const float* W2        = (const float*)d_in[4];
    const float* b0        = (const float*)d_in[5];
    const float* b1        = (const float*)d_in[6];
    const float* b2        = (const float*)d_in[7];
    const int4*  parent4   = (const int4*)d_in[8];
    const int4*  pix4      = (const int4*)d_in[9];
    float*       out       = (float*)d_out;

    // Host-side stream/events per call (tiny, no device memory). Capture is
    // in flight when we return, so these are intentionally not destroyed.
    cudaStream_t sb;
    cudaStreamCreateWithFlags(&sb, cudaStreamNonBlocking);

    cudaEvent_t evFork, evJoin, evC[NGRP];
    cudaEventCreateWithFlags(&evFork, cudaEventDisableTiming);
    cudaEventCreateWithFlags(&evJoin, cudaEventDisableTiming);
    for (int g = 0; g < NGRP; g++)
        cudaEventCreateWithFlags(&evC[g], cudaEventDisableTiming);

    cudaEventRecord(evFork, 0);
    cudaStreamWaitEvent(sb, evFork, 0);

    // ---- Full-width compute head ----
    k_contrib<<<TOTAL / 4 / 256, 256>>>(attrs4, residue4, parent4,
                                        W0, W1, W2, b0, b1, b2);
    k_prefix<<<NT, 1024>>>();

    {   // s0: [2048, 16384), all trees
        dim3 grid((16384 - 2048) / 256, NT);
        k_cascade<<<grid, 256>>>(0, 2048);
    }
    {   // s1: [16384, 131072), all trees
        dim3 grid((131072 - 16384) / 256, NT);
        k_cascade<<<grid, 256>>>(0, 16384);
    }

    // ---- Per-group tail: s2 + gather ----
    for (int g = 0; g < NGRP; g++) {
        const int base = g * TPG;
        {   // s2: [131072, 262144), 4 trees (grid 2048 blocks — still wide)
            dim3 grid((262144 - 131072) / 256, TPG);
            k_cascade<<<grid, 256>>>(base, 131072);
        }
        cudaEventRecord(evC[g], 0);
        cudaStreamWaitEvent(sb, evC[g], 0);
        {
            dim3 grid(HWPX / 4 / 256, TPG);
            k_gather<<<grid, 256, 0, sb>>>(base, pix4, out);
        }
    }

    cudaEventRecord(evJoin, sb);
    cudaStreamWaitEvent(0, evJoin, 0);
}

// round 8
// speedup vs baseline: 2.3553x; 1.0018x over previous
#include <cuda_runtime.h>

// Problem constants (fixed by the dataset)
#define NN      262144            // nodes per tree (2^18)
#define NT      12                // B*C trees
#define HWPX    1048576           // H*W (2^20)
#define T0      2048              // exactly-solved prefix per tree (2^11)
#define TOTAL   (NT * NN)
#define TPG     4                 // trees per pipeline group
#define NGRP    (NT / TPG)        // 3 groups

// Stage boundaries (full-width head stages, per-group tail stages)
#define S2_LO   32768
#define S2_HI   131072
#define S3_LO   131072
#define S3_HI   262144

// Blocks per tree for each role (256-thread blocks)
#define GB_TREE (HWPX / 4 / 256)            // 1024 gather blocks/tree
#define S3_TREE ((S3_HI - S3_LO) / 256)     // 512
#define S2_TREE ((S2_HI - S2_LO) / 256)     // 384
#define GB_GRP  (GB_TREE * TPG)             // 4096
#define S3_GRP  (S3_TREE * TPG)             // 2048
#define S2_GRP  (S2_TREE * TPG)             // 1536

// Scratch (allocation-free rule: __device__ globals)
__device__ float4 g_node[TOTAL];   // {c0,c1,c2,parent-as-float-bits}
__device__ float4 g_F[TOTAL];      // final {f0,f1,f2,_}

__device__ __forceinline__ float sigmoidf_(float x) {
    return 1.0f / (1.0f + expf(-x));
}

// ---------------------------------------------------------------------------
// Kernel A (full width): scores -> contrib, packed with parent pointer.
// ---------------------------------------------------------------------------
__global__ void k_contrib(const float4* __restrict__ attrs4,
                          const float4* __restrict__ residue4,
                          const int4*  __restrict__ parent4,
                          const float* __restrict__ W0,
                          const float* __restrict__ W1,
                          const float* __restrict__ W2,
                          const float* __restrict__ b0,
                          const float* __restrict__ b1,
                          const float* __restrict__ b2) {
    size_t q = (size_t)blockIdx.x * blockDim.x + threadIdx.x;

    float4 A0 = __ldcs(&attrs4[3 * q + 0]);   // a0[0] a1[0] a2[0] a0[1]
    float4 A1 = __ldcs(&attrs4[3 * q + 1]);   // a1[1] a2[1] a0[2] a1[2]
    float4 A2 = __ldcs(&attrs4[3 * q + 2]);   // a2[2] a0[3] a1[3] a2[3]
    float4 R  = __ldcs(&residue4[q]);
    int4   P  = __ldcs(&parent4[q]);

    const float w0  = __ldg(W0);
    const float w10 = __ldg(&W1[0]);
    const float w11 = __ldg(&W1[1]);
    const float w2  = __ldg(W2);
    const float B0 = __ldg(b0), B1 = __ldg(b1), B2 = __ldg(b2);

    float a0[4] = {A0.x, A0.w, A1.z, A2.y};
    float a1[4] = {A0.y, A1.x, A1.w, A2.z};
    float a2[4] = {A0.z, A1.y, A2.x, A2.w};
    float r[4]  = {R.x, R.y, R.z, R.w};
    int   p[4]  = {P.x, P.y, P.z, P.w};

    float4* outp = g_node + 4 * q;
#pragma unroll
    for (int k = 0; k < 4; k++) {
        float c0 = sigmoidf_(fmaf(a0[k], w0, B0)) * r[k];
        float c1 = sigmoidf_(fmaf(a2[k], w11, fmaf(a1[k], w10, B1))) * r[k];
        float c2 = sigmoidf_(fmaf(a1[k], w2, B2)) * r[k];
        outp[k] = make_float4(c0, c1, c2, __int_as_float(p[k]));
    }
}

// ---------------------------------------------------------------------------
// Kernel B (full width): exact prefix for nodes [0,T0) per tree, in-smem
// Wyllie jumping. grid = NT blocks x 1024 threads (block = tree).
// ---------------------------------------------------------------------------
__global__ void __launch_bounds__(1024, 1) k_prefix() {
    __shared__ float4 sm[T0];
    const int tree = blockIdx.x;
    const float4* nb = g_node + (size_t)tree * NN;

    for (int i = threadIdx.x; i < T0; i += blockDim.x)
        sm[i] = nb[i];
    __syncthreads();

    const int e0 = threadIdx.x;
    const int e1 = threadIdx.x + 1024;

    for (int r = 0; r < 11; r++) {
        float4 v0 = sm[e0];
        float4 v1 = sm[e1];
        int p0 = __float_as_int(v0.w);
        int p1 = __float_as_int(v1.w);
        if (p0 < T0) {
            float4 o = sm[p0];
            v0.x += o.x; v0.y += o.y; v0.z += o.z; v0.w = o.w;
        }
        if (p1 < T0) {
            float4 o = sm[p1];
            v1.x += o.x; v1.y += o.y; v1.z += o.z; v1.w = o.w;
        }
        __syncthreads();
        sm[e0] = v0;
        sm[e1] = v1;
        __syncthreads();
    }

    float4* Fb = g_F + (size_t)tree * NN;
    for (int i = threadIdx.x; i < T0; i += blockDim.x) {
        float4 v = sm[i];
        Fb[i] = make_float4(v.x, v.y, v.z, 0.0f);
    }
}

// ---------------------------------------------------------------------------
// Cascade body: finalize F for node n of `tree`; everything below `start`
// is already final in g_F.
// ---------------------------------------------------------------------------
__device__ __forceinline__ void cascade_body(int tree, int start, int n) {
    const float4* nb = g_node + (size_t)tree * NN;
    float4*       Fb = g_F    + (size_t)tree * NN;

    float4 v = __ldg(&nb[n]);
    float ax = v.x, ay = v.y, az = v.z;
    int p = __float_as_int(v.w);

    while (p >= start) {
        float4 u = __ldg(&nb[p]);
        ax += u.x; ay += u.y; az += u.z;
        p = __float_as_int(u.w);
    }
    float4 f = __ldg(&Fb[p]);
    Fb[n] = make_float4(ax + f.x, ay + f.y, az + f.z, 0.0f);
}

// Plain cascade kernel (head stages): trees [base, base+gridDim.y)
__global__ void k_cascade(int base, int start) {
    const int tree = base + blockIdx.y;
    const int n = start + blockIdx.x * blockDim.x + threadIdx.x;
    cascade_body(tree, start, n);
}

// ---------------------------------------------------------------------------
// Gather body: 4 pixels/thread for `tree`; one 16B gather serves all 3
// output channels; coalesced float4 stores per channel plane.
// ---------------------------------------------------------------------------
__device__ __forceinline__ void gather_body(int tree, int lt,
                                            const int4* __restrict__ pix4,
                                            float* __restrict__ out) {
    int4 nd = __ldcs(&pix4[(size_t)tree * (HWPX / 4) + lt]);

    const float4* Fb = g_F + (size_t)tree * NN;
    float4 F0 = __ldg(&Fb[nd.x]);
    float4 F1 = __ldg(&Fb[nd.y]);
    float4 F2 = __ldg(&Fb[nd.z]);
    float4 F3 = __ldg(&Fb[nd.w]);

    float* o = out + (size_t)tree * 3 * HWPX + 4 * (size_t)lt;
    __stcs((float4*)(o),            make_float4(F0.x, F1.x, F2.x, F3.x));
    __stcs((float4*)(o + HWPX),     make_float4(F0.y, F1.y, F2.y, F3.y));
    __stcs((float4*)(o + 2 * HWPX), make_float4(F0.z, F1.z, F2.z, F3.z));
}

// ---------------------------------------------------------------------------
// Mixed-role kernel: heterogeneous blocks, ALL runnable at launch (deps of
// every role completed in previous kernels; no cross-block waiting).
// Block layout (in bid order): [gather gbase | s3 s3base | s2 s2base],
// any role disabled with base = -1. Gather blocks take the low bids so the
// long-pole work launches first; cascades fill the issue/latency slack.
// ---------------------------------------------------------------------------
__global__ void k_mix(int gbase, int s3base, int s2base,
                      const int4* __restrict__ pix4,
                      float* __restrict__ out) {
    int bid = blockIdx.x;

    if (gbase >= 0) {
        if (bid < GB_GRP) {
            const int tree = gbase + bid / GB_TREE;
            const int lt = (bid % GB_TREE) * 256 + threadIdx.x;
            gather_body(tree, lt, pix4, out);
            return;
        }
        bid -= GB_GRP;
    }
    if (s3base >= 0) {
        if (bid < S3_GRP) {
            const int tree = s3base + bid / S3_TREE;
            const int n = S3_LO + (bid % S3_TREE) * 256 + threadIdx.x;
            cascade_body(tree, S3_LO, n);
            return;
        }
        bid -= S3_GRP;
    }
    // s2 role
    {
        const int tree = s2base + bid / S2_TREE;
        const int n = S2_LO + (bid % S2_TREE) * 256 + threadIdx.x;
        cascade_body(tree, S2_LO, n);
    }
}

// ---------------------------------------------------------------------------
// Entry point — single stream, 9 plain serial launches; overlap comes from
// heterogeneous blocks inside K6..K8, not from the scheduler.
// Inputs: attrs, residue, W0, W1, W2, b0, b1, b2, parent, pixel_node
// ---------------------------------------------------------------------------
extern "C" void kernel_launch(void* const* d_in, const int* in_sizes, int n_in,
                              void* d_out, int out_size) {
    const float4* attrs4   = (const float4*)d_in[0];
    const float4* residue4 = (const float4*)d_in[1];
    const float* W0        = (const float*)d_in[2];
    const float* W1        = (const float*)d_in[3];
    const float* W2        = (const float*)d_in[4];
    const float* b0        = (const float*)d_in[5];
    const float* b1        = (const float*)d_in[6];
    const float* b2        = (const float*)d_in[7];
    const int4*  parent4   = (const int4*)d_in[8];
    const int4*  pix4      = (const int4*)d_in[9];
    float*       out       = (float*)d_out;

    // K1: contrib, all trees
    k_contrib<<<TOTAL / 4 / 256, 256>>>(attrs4, residue4, parent4,
                                        W0, W1, W2, b0, b1, b2);
    // K2: prefix, all trees
    k_prefix<<<NT, 1024>>>();

    // K3: s0 [2048, 8192), all trees
    {
        dim3 grid((8192 - 2048) / 256, NT);
        k_cascade<<<grid, 256>>>(0, 2048);
    }
    // K4: s1 [8192, 32768), all trees
    {
        dim3 grid((32768 - 8192) / 256, NT);
        k_cascade<<<grid, 256>>>(0, 8192);
    }
    // K5: s2 [32768, 131072), group 0 only
    {
        dim3 grid(S2_TREE, TPG);
        k_cascade<<<grid, 256>>>(0, S2_LO);
    }
    // K6: s3(G0) || s2(G1)
    k_mix<<<S3_GRP + S2_GRP, 256>>>(-1, 0, TPG, pix4, out);
    // K7: gather(G0) || s3(G1) || s2(G2)
    k_mix<<<GB_GRP + S3_GRP + S2_GRP, 256>>>(0, TPG, 2 * TPG, pix4, out);
    // K8: gather(G1) || s3(G2)
    k_mix<<<GB_GRP + S3_GRP, 256>>>(TPG, 2 * TPG, -999, pix4, out);
    // K9: gather(G2)
    k_mix<<<GB_GRP, 256>>>(2 * TPG, -1, -999, pix4, out);
}